// round 7
// baseline (speedup 1.0000x reference)
#include <cuda_runtime.h>
#include <cuda_bf16.h>

#define N_NODES   1000000
#define D_FEAT    128
#define B_SEGS    1024
#define NWARPS    8
#define NTHREADS  (NWARPS * 32)
#define BLOCKS_PER_SM 5
#define GRID_A    (148 * BLOCKS_PER_SM)     // 740 blocks -> exactly one wave
#define TOT_WARPS (GRID_A * NWARPS)         // 5920
#define ROWS_PW   169                       // ceil(1e6 / 5920)

// Device scratch (no allocations allowed).
__device__ float g_e[N_NODES];              // exp(gate) per node
__device__ float g_S[B_SEGS];               // per-segment exp-sum
__device__ float g_W[B_SEGS * D_FEAT];      // per-segment weighted sum

// ---------------------------------------------------------------- zero scratch
__global__ void zero_scratch_kernel() {
    int i = blockIdx.x * blockDim.x + threadIdx.x;
    if (i < B_SEGS) g_S[i] = 0.f;
    if (i < B_SEGS * D_FEAT) g_W[i] = 0.f;
}

// ------------------------------------------------------- main fused pass over feat
__global__ __launch_bounds__(NTHREADS, BLOCKS_PER_SM)
void gap_main_kernel(const float* __restrict__ feat,
                     const float* __restrict__ w_gate,
                     const float* __restrict__ b_gate,
                     const int*   __restrict__ seg)
{
    const int tid  = threadIdx.x;
    const int wid  = tid >> 5;
    const int lane = tid & 31;

    const int gw     = blockIdx.x * NWARPS + wid;        // global warp id
    const int wstart = gw * ROWS_PW;
    const int wend   = min(wstart + ROWS_PW, N_NODES);
    if (wstart >= wend) return;

    const float  bg = b_gate[0];
    const float4 w4 = reinterpret_cast<const float4*>(w_gate)[lane];
    const float4* __restrict__ feat4 = reinterpret_cast<const float4*>(feat);

    int    cur  = seg[wstart];                // warp-uniform
    float  Ssum = 0.f;
    float4 acc  = make_float4(0.f, 0.f, 0.f, 0.f);

    int n = wstart;
    while (n < wend) {
        if (n + 3 < wend && seg[n] == cur && seg[n + 3] == cur) {
            // ---- fast path: 4 rows, same segment (sorted => all 4 equal) ----
            const float4 f0 = __ldg(feat4 + (size_t)(n + 0) * 32 + lane);
            const float4 f1 = __ldg(feat4 + (size_t)(n + 1) * 32 + lane);
            const float4 f2 = __ldg(feat4 + (size_t)(n + 2) * 32 + lane);
            const float4 f3 = __ldg(feat4 + (size_t)(n + 3) * 32 + lane);

            float p0 = f0.x*w4.x + f0.y*w4.y + f0.z*w4.z + f0.w*w4.w;
            float p1 = f1.x*w4.x + f1.y*w4.y + f1.z*w4.z + f1.w*w4.w;
            float p2 = f2.x*w4.x + f2.y*w4.y + f2.z*w4.z + f2.w*w4.w;
            float p3 = f3.x*w4.x + f3.y*w4.y + f3.z*w4.z + f3.w*w4.w;
            #pragma unroll
            for (int s = 16; s >= 1; s >>= 1) {     // 4 interleaved butterfly chains
                p0 += __shfl_xor_sync(0xffffffffu, p0, s);
                p1 += __shfl_xor_sync(0xffffffffu, p1, s);
                p2 += __shfl_xor_sync(0xffffffffu, p2, s);
                p3 += __shfl_xor_sync(0xffffffffu, p3, s);
            }
            const float e0 = __expf(p0 + bg);
            const float e1 = __expf(p1 + bg);
            const float e2 = __expf(p2 + bg);
            const float e3 = __expf(p3 + bg);
            if (lane < 4) {
                float ev = (lane == 0) ? e0 : (lane == 1) ? e1 : (lane == 2) ? e2 : e3;
                g_e[n + lane] = ev;
            }
            Ssum += (e0 + e1) + (e2 + e3);
            acc.x += e0*f0.x + e1*f1.x + e2*f2.x + e3*f3.x;
            acc.y += e0*f0.y + e1*f1.y + e2*f2.y + e3*f3.y;
            acc.z += e0*f0.z + e1*f1.z + e2*f2.z + e3*f3.z;
            acc.w += e0*f0.w + e1*f1.w + e2*f2.w + e3*f3.w;
            n += 4;
        } else {
            // ---- slow path: one row, possible segment boundary ----
            const int s = seg[n];
            if (s != cur) {
                // flush warp-private partials for finished segment
                if (lane == 0) atomicAdd(&g_S[cur], Ssum);
                float* wp = &g_W[(size_t)cur * D_FEAT + lane * 4];
                atomicAdd(wp + 0, acc.x);
                atomicAdd(wp + 1, acc.y);
                atomicAdd(wp + 2, acc.z);
                atomicAdd(wp + 3, acc.w);
                cur = s; Ssum = 0.f; acc = make_float4(0.f, 0.f, 0.f, 0.f);
            }
            const float4 f = __ldg(feat4 + (size_t)n * 32 + lane);
            float p = f.x*w4.x + f.y*w4.y + f.z*w4.z + f.w*w4.w;
            #pragma unroll
            for (int sh = 16; sh >= 1; sh >>= 1)
                p += __shfl_xor_sync(0xffffffffu, p, sh);
            const float e = __expf(p + bg);
            if (lane == 0) g_e[n] = e;
            Ssum += e;
            acc.x += e*f.x; acc.y += e*f.y; acc.z += e*f.z; acc.w += e*f.w;
            n += 1;
        }
    }
    // final flush
    if (lane == 0) atomicAdd(&g_S[cur], Ssum);
    float* wp = &g_W[(size_t)cur * D_FEAT + lane * 4];
    atomicAdd(wp + 0, acc.x);
    atomicAdd(wp + 1, acc.y);
    atomicAdd(wp + 2, acc.z);
    atomicAdd(wp + 3, acc.w);
}

__device__ __forceinline__ int lower_bound_i32(const int* __restrict__ a, int n, int v) {
    int lo = 0, hi = n;
    while (lo < hi) {
        int m = (lo + hi) >> 1;
        if (a[m] < v) lo = m + 1; else hi = m;
    }
    return lo;
}

// ------------------- merged finalize + alpha: one block per segment ------------
// Computes invS, writes the readout row, then streams alpha for this segment's
// node range (g_e is L2-hot from the main kernel; seg read only via binary search).
__global__ __launch_bounds__(256)
void gap_finalize_alpha_kernel(const int* __restrict__ seg,
                               float* __restrict__ readout,
                               float* __restrict__ alpha,
                               int n_nodes)
{
    __shared__ int   s_bounds[2];
    __shared__ float s_invS;

    const int b   = blockIdx.x;
    const int tid = threadIdx.x;

    if (tid < 2) s_bounds[tid] = lower_bound_i32(seg, n_nodes, b + tid);
    if (tid == 0) {
        const float S = g_S[b];
        s_invS = (S > 0.f) ? (1.0f / S) : 0.0f;
    }
    __syncthreads();

    const int   start = s_bounds[0];
    const int   end   = s_bounds[1];
    const float invS  = s_invS;

    // readout row (128 columns)
    if (tid < D_FEAT)
        readout[(size_t)b * D_FEAT + tid] = g_W[(size_t)b * D_FEAT + tid] * invS;

    // alpha for this segment's nodes (L2-hit reads of g_e, streaming writes)
    for (int n = start + tid; n < end; n += 256)
        alpha[n] = g_e[n] * invS;
}

extern "C" void kernel_launch(void* const* d_in, const int* in_sizes, int n_in,
                              void* d_out, int out_size)
{
    const float* feat   = (const float*)d_in[0];
    const float* w_gate = (const float*)d_in[1];
    const float* b_gate = (const float*)d_in[2];
    const int*   seg    = (const int*)d_in[3];
    const int    n      = in_sizes[3];

    float* out     = (float*)d_out;
    float* readout = out;                            // [B, D]
    float* alpha   = out + (size_t)B_SEGS * D_FEAT;  // [N, 1]

    zero_scratch_kernel<<<(B_SEGS * D_FEAT + 255) / 256, 256>>>();
    gap_main_kernel<<<GRID_A, NTHREADS>>>(feat, w_gate, b_gate, seg);
    gap_finalize_alpha_kernel<<<B_SEGS, 256>>>(seg, readout, alpha, n);
}

// round 8
// speedup vs baseline: 1.0630x; 1.0630x over previous
#include <cuda_runtime.h>
#include <cuda_bf16.h>

#define N_NODES   1000000
#define D_FEAT    128
#define B_SEGS    1024
#define NWARPS    8
#define NTHREADS  (NWARPS * 32)
#define BLOCKS_PER_SM 5
#define GRID_A    (148 * BLOCKS_PER_SM)     // 740 blocks -> exactly one wave
#define TOT_WARPS (GRID_A * NWARPS)         // 5920
#define ROWS_PW   169                       // ceil(1e6 / 5920)

// Device scratch (no allocations allowed). Zero-initialized at module load;
// the finalize kernel restores g_S/g_W to zero after each use, so every
// graph replay sees zeroed accumulators without a dedicated zeroing launch.
__device__ float g_e[N_NODES];              // exp(gate) per node
__device__ float g_S[B_SEGS];               // per-segment exp-sum
__device__ float g_W[B_SEGS * D_FEAT];      // per-segment weighted sum
__device__ int   g_start[B_SEGS + 1];       // per-segment start offsets

// ---------------- segment boundary detection: one streaming pass over seg ----
// Every b in [0, B_SEGS] is written by exactly one thread (sorted seg =>
// unique transition). Empty segments land with start == end.
__global__ __launch_bounds__(256)
void seg_starts_kernel(const int* __restrict__ seg, int n_nodes)
{
    const int i  = blockIdx.x * blockDim.x + threadIdx.x;
    const int n0 = i * 4;
    if (n0 >= n_nodes) return;

    const int4 s = *reinterpret_cast<const int4*>(seg + n0);
    const int nxt = (n0 + 4 < n_nodes) ? seg[n0 + 4] : B_SEGS;
    int a0 = s.x, a1 = s.y, a2 = s.z, a3 = s.w, a4 = nxt;

    if (n0 == 0)
        for (int b = 0; b <= a0; b++) g_start[b] = 0;

    for (int b = a0 + 1; b <= a1; b++) g_start[b] = n0 + 1;
    for (int b = a1 + 1; b <= a2; b++) g_start[b] = n0 + 2;
    for (int b = a2 + 1; b <= a3; b++) g_start[b] = n0 + 3;
    for (int b = a3 + 1; b <= a4; b++) g_start[b] = n0 + 4;
}

// ------------------------------------------------------- main fused pass over feat
__global__ __launch_bounds__(NTHREADS, BLOCKS_PER_SM)
void gap_main_kernel(const float* __restrict__ feat,
                     const float* __restrict__ w_gate,
                     const float* __restrict__ b_gate,
                     const int*   __restrict__ seg)
{
    const int tid  = threadIdx.x;
    const int wid  = tid >> 5;
    const int lane = tid & 31;

    const int gw     = blockIdx.x * NWARPS + wid;        // global warp id
    const int wstart = gw * ROWS_PW;
    const int wend   = min(wstart + ROWS_PW, N_NODES);
    if (wstart >= wend) return;

    const float  bg = b_gate[0];
    const float4 w4 = reinterpret_cast<const float4*>(w_gate)[lane];
    const float4* __restrict__ feat4 = reinterpret_cast<const float4*>(feat);

    int    cur  = seg[wstart];                // warp-uniform
    float  Ssum = 0.f;
    float4 acc  = make_float4(0.f, 0.f, 0.f, 0.f);

    int n = wstart;
    while (n < wend) {
        if (n + 3 < wend && seg[n] == cur && seg[n + 3] == cur) {
            // ---- fast path: 4 rows, same segment (sorted => all 4 equal) ----
            const float4 f0 = __ldg(feat4 + (size_t)(n + 0) * 32 + lane);
            const float4 f1 = __ldg(feat4 + (size_t)(n + 1) * 32 + lane);
            const float4 f2 = __ldg(feat4 + (size_t)(n + 2) * 32 + lane);
            const float4 f3 = __ldg(feat4 + (size_t)(n + 3) * 32 + lane);

            float p0 = f0.x*w4.x + f0.y*w4.y + f0.z*w4.z + f0.w*w4.w;
            float p1 = f1.x*w4.x + f1.y*w4.y + f1.z*w4.z + f1.w*w4.w;
            float p2 = f2.x*w4.x + f2.y*w4.y + f2.z*w4.z + f2.w*w4.w;
            float p3 = f3.x*w4.x + f3.y*w4.y + f3.z*w4.z + f3.w*w4.w;
            #pragma unroll
            for (int s = 16; s >= 1; s >>= 1) {     // 4 interleaved butterfly chains
                p0 += __shfl_xor_sync(0xffffffffu, p0, s);
                p1 += __shfl_xor_sync(0xffffffffu, p1, s);
                p2 += __shfl_xor_sync(0xffffffffu, p2, s);
                p3 += __shfl_xor_sync(0xffffffffu, p3, s);
            }
            const float e0 = __expf(p0 + bg);
            const float e1 = __expf(p1 + bg);
            const float e2 = __expf(p2 + bg);
            const float e3 = __expf(p3 + bg);
            if (lane < 4) {
                float ev = (lane == 0) ? e0 : (lane == 1) ? e1 : (lane == 2) ? e2 : e3;
                g_e[n + lane] = ev;
            }
            Ssum += (e0 + e1) + (e2 + e3);
            acc.x += e0*f0.x + e1*f1.x + e2*f2.x + e3*f3.x;
            acc.y += e0*f0.y + e1*f1.y + e2*f2.y + e3*f3.y;
            acc.z += e0*f0.z + e1*f1.z + e2*f2.z + e3*f3.z;
            acc.w += e0*f0.w + e1*f1.w + e2*f2.w + e3*f3.w;
            n += 4;
        } else {
            // ---- slow path: one row, possible segment boundary ----
            const int s = seg[n];
            if (s != cur) {
                // flush warp-private partials for finished segment
                if (lane == 0) atomicAdd(&g_S[cur], Ssum);
                float* wp = &g_W[(size_t)cur * D_FEAT + lane * 4];
                atomicAdd(wp + 0, acc.x);
                atomicAdd(wp + 1, acc.y);
                atomicAdd(wp + 2, acc.z);
                atomicAdd(wp + 3, acc.w);
                cur = s; Ssum = 0.f; acc = make_float4(0.f, 0.f, 0.f, 0.f);
            }
            const float4 f = __ldg(feat4 + (size_t)n * 32 + lane);
            float p = f.x*w4.x + f.y*w4.y + f.z*w4.z + f.w*w4.w;
            #pragma unroll
            for (int sh = 16; sh >= 1; sh >>= 1)
                p += __shfl_xor_sync(0xffffffffu, p, sh);
            const float e = __expf(p + bg);
            if (lane == 0) g_e[n] = e;
            Ssum += e;
            acc.x += e*f.x; acc.y += e*f.y; acc.z += e*f.z; acc.w += e*f.w;
            n += 1;
        }
    }
    // final flush
    if (lane == 0) atomicAdd(&g_S[cur], Ssum);
    float* wp = &g_W[(size_t)cur * D_FEAT + lane * 4];
    atomicAdd(wp + 0, acc.x);
    atomicAdd(wp + 1, acc.y);
    atomicAdd(wp + 2, acc.z);
    atomicAdd(wp + 3, acc.w);
}

// ---------------- finalize + alpha, one block per segment -------------------
// Flat loads of precomputed bounds (no binary search), block-uniform invS (no
// scattered gather), and zero-restore of the accumulators for the next replay.
__global__ __launch_bounds__(256)
void gap_finalize_alpha_kernel(float* __restrict__ readout,
                               float* __restrict__ alpha)
{
    const int b   = blockIdx.x;
    const int tid = threadIdx.x;

    const int start = g_start[b];
    const int end   = g_start[b + 1];
    const float S   = g_S[b];
    const float invS = (S > 0.f) ? (1.0f / S) : 0.0f;

    if (tid < D_FEAT) {
        const size_t idx = (size_t)b * D_FEAT + tid;
        readout[idx] = g_W[idx] * invS;
        g_W[idx] = 0.f;                         // restore zeros for next replay
    }
    if (tid == 0) g_S[b] = 0.f;

    for (int n = start + tid; n < end; n += 256)
        alpha[n] = g_e[n] * invS;
}

extern "C" void kernel_launch(void* const* d_in, const int* in_sizes, int n_in,
                              void* d_out, int out_size)
{
    const float* feat   = (const float*)d_in[0];
    const float* w_gate = (const float*)d_in[1];
    const float* b_gate = (const float*)d_in[2];
    const int*   seg    = (const int*)d_in[3];
    const int    n      = in_sizes[3];

    float* out     = (float*)d_out;
    float* readout = out;                            // [B, D]
    float* alpha   = out + (size_t)B_SEGS * D_FEAT;  // [N, 1]

    seg_starts_kernel<<<(N_NODES / 4 + 255) / 256, 256>>>(seg, n);
    gap_main_kernel<<<GRID_A, NTHREADS>>>(feat, w_gate, b_gate, seg);
    gap_finalize_alpha_kernel<<<B_SEGS, 256>>>(readout, alpha);
}

// round 9
// speedup vs baseline: 1.1064x; 1.0407x over previous
#include <cuda_runtime.h>
#include <cuda_bf16.h>

#define N_NODES   1000000
#define D_FEAT    128
#define B_SEGS    1024
#define NWARPS    8
#define NTHREADS  (NWARPS * 32)
#define BLOCKS_PER_SM 5
#define GRID_A    (148 * BLOCKS_PER_SM)     // 740 blocks -> exactly one wave
#define TOT_WARPS (GRID_A * NWARPS)         // 5920
#define ROWS_PW   169                       // ceil(1e6 / 5920)

// Device scratch (no allocations allowed). Zero-initialized at module load;
// the finalize kernel restores g_S/g_W to zero after each use, so every
// graph replay sees zeroed accumulators without a dedicated zeroing launch.
// g_start is fully rewritten by the main kernel each replay.
__device__ float g_e[N_NODES];              // exp(gate) per node
__device__ float g_S[B_SEGS];               // per-segment exp-sum
__device__ float g_W[B_SEGS * D_FEAT];      // per-segment weighted sum
__device__ int   g_start[B_SEGS + 1];       // per-segment start offsets

// ------------------------------------------------------- main fused pass over feat
// Also performs segment-boundary detection inline: every transition index is
// encountered exactly once (in the slow path or a warp prologue), so g_start
// is complete when this kernel finishes.
__global__ __launch_bounds__(NTHREADS, BLOCKS_PER_SM)
void gap_main_kernel(const float* __restrict__ feat,
                     const float* __restrict__ w_gate,
                     const float* __restrict__ b_gate,
                     const int*   __restrict__ seg)
{
    const int tid  = threadIdx.x;
    const int wid  = tid >> 5;
    const int lane = tid & 31;

    const int gw     = blockIdx.x * NWARPS + wid;        // global warp id
    const int wstart = gw * ROWS_PW;
    const int wend   = min(wstart + ROWS_PW, N_NODES);
    if (wstart >= wend) return;

    const float  bg = b_gate[0];
    const float4 w4 = reinterpret_cast<const float4*>(w_gate)[lane];
    const float4* __restrict__ feat4 = reinterpret_cast<const float4*>(feat);

    int    cur  = seg[wstart];                // warp-uniform
    float  Ssum = 0.f;
    float4 acc  = make_float4(0.f, 0.f, 0.f, 0.f);

    // ---- boundary prologue: transitions landing exactly at wstart ----
    if (lane == 0) {
        if (wstart == 0) {
            for (int b = 0; b <= cur; b++) g_start[b] = 0;
        } else {
            const int prev = seg[wstart - 1];
            for (int b = prev + 1; b <= cur; b++) g_start[b] = wstart;
        }
    }

    int n = wstart;
    while (n < wend) {
        if (n + 3 < wend && seg[n] == cur && seg[n + 3] == cur) {
            // ---- fast path: 4 rows, same segment (sorted => all 4 equal) ----
            const float4 f0 = __ldg(feat4 + (size_t)(n + 0) * 32 + lane);
            const float4 f1 = __ldg(feat4 + (size_t)(n + 1) * 32 + lane);
            const float4 f2 = __ldg(feat4 + (size_t)(n + 2) * 32 + lane);
            const float4 f3 = __ldg(feat4 + (size_t)(n + 3) * 32 + lane);

            float p0 = f0.x*w4.x + f0.y*w4.y + f0.z*w4.z + f0.w*w4.w;
            float p1 = f1.x*w4.x + f1.y*w4.y + f1.z*w4.z + f1.w*w4.w;
            float p2 = f2.x*w4.x + f2.y*w4.y + f2.z*w4.z + f2.w*w4.w;
            float p3 = f3.x*w4.x + f3.y*w4.y + f3.z*w4.z + f3.w*w4.w;
            #pragma unroll
            for (int s = 16; s >= 1; s >>= 1) {     // 4 interleaved butterfly chains
                p0 += __shfl_xor_sync(0xffffffffu, p0, s);
                p1 += __shfl_xor_sync(0xffffffffu, p1, s);
                p2 += __shfl_xor_sync(0xffffffffu, p2, s);
                p3 += __shfl_xor_sync(0xffffffffu, p3, s);
            }
            const float e0 = __expf(p0 + bg);
            const float e1 = __expf(p1 + bg);
            const float e2 = __expf(p2 + bg);
            const float e3 = __expf(p3 + bg);
            if (lane < 4) {
                float ev = (lane == 0) ? e0 : (lane == 1) ? e1 : (lane == 2) ? e2 : e3;
                g_e[n + lane] = ev;
            }
            Ssum += (e0 + e1) + (e2 + e3);
            acc.x += e0*f0.x + e1*f1.x + e2*f2.x + e3*f3.x;
            acc.y += e0*f0.y + e1*f1.y + e2*f2.y + e3*f3.y;
            acc.z += e0*f0.z + e1*f1.z + e2*f2.z + e3*f3.z;
            acc.w += e0*f0.w + e1*f1.w + e2*f2.w + e3*f3.w;
            n += 4;
        } else {
            // ---- slow path: one row, possible segment boundary ----
            const int s = seg[n];
            if (s != cur) {
                // record boundary + flush warp-private partials
                if (lane == 0) {
                    for (int b = cur + 1; b <= s; b++) g_start[b] = n;
                    atomicAdd(&g_S[cur], Ssum);
                }
                float* wp = &g_W[(size_t)cur * D_FEAT + lane * 4];
                atomicAdd(wp + 0, acc.x);
                atomicAdd(wp + 1, acc.y);
                atomicAdd(wp + 2, acc.z);
                atomicAdd(wp + 3, acc.w);
                cur = s; Ssum = 0.f; acc = make_float4(0.f, 0.f, 0.f, 0.f);
            }
            const float4 f = __ldg(feat4 + (size_t)n * 32 + lane);
            float p = f.x*w4.x + f.y*w4.y + f.z*w4.z + f.w*w4.w;
            #pragma unroll
            for (int sh = 16; sh >= 1; sh >>= 1)
                p += __shfl_xor_sync(0xffffffffu, p, sh);
            const float e = __expf(p + bg);
            if (lane == 0) g_e[n] = e;
            Ssum += e;
            acc.x += e*f.x; acc.y += e*f.y; acc.z += e*f.z; acc.w += e*f.w;
            n += 1;
        }
    }

    // ---- final flush + boundary epilogue ----
    if (lane == 0) {
        atomicAdd(&g_S[cur], Ssum);
        if (wend == N_NODES)
            for (int b = cur + 1; b <= B_SEGS; b++) g_start[b] = N_NODES;
    }
    float* wp = &g_W[(size_t)cur * D_FEAT + lane * 4];
    atomicAdd(wp + 0, acc.x);
    atomicAdd(wp + 1, acc.y);
    atomicAdd(wp + 2, acc.z);
    atomicAdd(wp + 3, acc.w);
}

// ---------------- finalize + alpha, one block per segment -------------------
// Flat loads of precomputed bounds (no binary search), block-uniform invS (no
// scattered gather), and zero-restore of the accumulators for the next replay.
__global__ __launch_bounds__(256)
void gap_finalize_alpha_kernel(float* __restrict__ readout,
                               float* __restrict__ alpha)
{
    const int b   = blockIdx.x;
    const int tid = threadIdx.x;

    const int start = g_start[b];
    const int end   = g_start[b + 1];
    const float S   = g_S[b];
    const float invS = (S > 0.f) ? (1.0f / S) : 0.0f;

    if (tid < D_FEAT) {
        const size_t idx = (size_t)b * D_FEAT + tid;
        readout[idx] = g_W[idx] * invS;
        g_W[idx] = 0.f;                         // restore zeros for next replay
    }
    if (tid == 0) g_S[b] = 0.f;

    for (int n = start + tid; n < end; n += 256)
        alpha[n] = g_e[n] * invS;
}

extern "C" void kernel_launch(void* const* d_in, const int* in_sizes, int n_in,
                              void* d_out, int out_size)
{
    const float* feat   = (const float*)d_in[0];
    const float* w_gate = (const float*)d_in[1];
    const float* b_gate = (const float*)d_in[2];
    const int*   seg    = (const int*)d_in[3];

    float* out     = (float*)d_out;
    float* readout = out;                            // [B, D]
    float* alpha   = out + (size_t)B_SEGS * D_FEAT;  // [N, 1]

    gap_main_kernel<<<GRID_A, NTHREADS>>>(feat, w_gate, b_gate, seg);
    gap_finalize_alpha_kernel<<<B_SEGS, 256>>>(readout, alpha);
}